// round 6
// baseline (speedup 1.0000x reference)
#include <cuda_runtime.h>
#include <cstdint>

#define D        256
#define MAXN     50000
#define MAXE     800000
#define BM       64
#define BK       16

// ---------------- scratch (no allocations allowed) ----------------
__device__ __align__(16) float g_agg[(size_t)MAXN * D];  // normalized mean-agg
__device__ __align__(16) float g_h[(size_t)MAXN * D];    // hidden activations
__device__ int g_cnt[MAXN];       // in-degree
__device__ int g_off[MAXN];       // CSR row offsets
__device__ int g_pos[MAXN];       // fill cursor for CSR build
__device__ int g_csr_src[MAXE];   // src node per edge, grouped by tgt
__device__ int g_src[MAXE];       // decoded src indices (int32)
__device__ int g_tgt[MAXE];       // decoded tgt indices (int32)
__device__ int g_flag;            // 0 => edge dtype int64, nonzero => int32

// ---------------- edge dtype detect + decode ----------------
// Probe odd int32 words of the first n_edges int64-candidates (words
// [0, 2*n_edges) are in-bounds for BOTH dtypes). If the buffer is int64
// (values < 2^31), all odd words are 0. If int32, they're random indices.
__global__ void detect_kernel(const int* __restrict__ raw, int n_edges) {
    int i = blockIdx.x * blockDim.x + threadIdx.x;
    if (i == 0 && blockIdx.x == 0) { /* no-op */ }
    if (i < n_edges) {
        int v = raw[2 * i + 1];
        if (v != 0) atomicOr(&g_flag, 1);
    }
}

__global__ void zero_flag_kernel() { g_flag = 0; }

__global__ void extract_kernel(const int* __restrict__ raw,
                               int n_edges, int n_nodes) {
    int e = blockIdx.x * blockDim.x + threadIdx.x;
    if (e >= n_edges) return;
    int s, t;
    if (g_flag == 0) {             // int64 layout: low word of each int64
        s = raw[2 * e];
        t = raw[2 * (n_edges + e)];
    } else {                       // int32 layout
        s = raw[e];
        t = raw[n_edges + e];
    }
    // defensive clamp (reference indices are always in range)
    s = min(max(s, 0), n_nodes - 1);
    t = min(max(t, 0), n_nodes - 1);
    g_src[e] = s;
    g_tgt[e] = t;
}

// ---------------- CSR build ----------------
__global__ void zero_cnt_kernel(int n) {
    int i = blockIdx.x * blockDim.x + threadIdx.x;
    if (i < n) g_cnt[i] = 0;
}

__global__ void count_kernel(int n_edges) {
    int e = blockIdx.x * blockDim.x + threadIdx.x;
    if (e < n_edges) atomicAdd(&g_cnt[g_tgt[e]], 1);
}

// single-block exclusive scan of g_cnt -> g_off, g_pos
__global__ void scan_kernel(int n) {
    const int T = 1024;
    __shared__ int sh[T];
    int tid = threadIdx.x;
    int chunk = (n + T - 1) / T;
    int start = tid * chunk;
    int end   = min(start + chunk, n);

    int sum = 0;
    for (int i = start; i < end; i++) sum += g_cnt[i];
    sh[tid] = sum;
    __syncthreads();

    for (int off = 1; off < T; off <<= 1) {
        int v = (tid >= off) ? sh[tid - off] : 0;
        __syncthreads();
        sh[tid] += v;
        __syncthreads();
    }
    int run = (tid == 0) ? 0 : sh[tid - 1];
    for (int i = start; i < end; i++) {
        g_off[i] = run;
        g_pos[i] = run;
        run += g_cnt[i];
    }
}

__global__ void build_kernel(int n_edges) {
    int e = blockIdx.x * blockDim.x + threadIdx.x;
    if (e < n_edges) {
        int p = atomicAdd(&g_pos[g_tgt[e]], 1);
        g_csr_src[p] = g_src[e];
    }
}

// ---------------- gather mean-aggregate: one warp per node ----------------
__global__ void __launch_bounds__(256)
aggregate_kernel(const float* __restrict__ feat, int n_nodes) {
    int warp = (blockIdx.x * blockDim.x + threadIdx.x) >> 5;
    int lane = threadIdx.x & 31;
    if (warp >= n_nodes) return;

    int beg = g_off[warp];
    int deg = g_cnt[warp];

    float4 a0 = make_float4(0.f, 0.f, 0.f, 0.f);
    float4 a1 = make_float4(0.f, 0.f, 0.f, 0.f);
    for (int i = 0; i < deg; i++) {
        int s = __ldg(&g_csr_src[beg + i]);
        const float4* fs = (const float4*)(feat + (size_t)s * D);
        float4 v0 = fs[lane];
        float4 v1 = fs[lane + 32];
        a0.x += v0.x; a0.y += v0.y; a0.z += v0.z; a0.w += v0.w;
        a1.x += v1.x; a1.y += v1.y; a1.z += v1.z; a1.w += v1.w;
    }
    float iv = 1.0f / (float)(deg > 1 ? deg : 1);
    a0.x *= iv; a0.y *= iv; a0.z *= iv; a0.w *= iv;
    a1.x *= iv; a1.y *= iv; a1.z *= iv; a1.w *= iv;

    float4* out = (float4*)(g_agg + (size_t)warp * D);
    out[lane]      = a0;
    out[lane + 32] = a1;
}

// ---------------- fused SAGE GEMM ----------------
// out[row,:] = act( g_agg[row,:] @ Wl + xin[row,:] @ Wr + bias )
// Virtual A = [g_agg | xin] (K=512), virtual B = [Wl ; Wr].
// BM=64, BN=256, BK=16, 256 threads; 8x8 micro-tile per thread,
// accumulated as 32 packed f32x2 (fma.rn.f32x2).
__global__ void __launch_bounds__(256, 2)
sage_gemm_kernel(const float* __restrict__ xin,
                 const float* __restrict__ Wl,
                 const float* __restrict__ bias,
                 const float* __restrict__ Wr,
                 float* __restrict__ out,
                 int n_nodes, int do_relu) {
    __shared__ float As[BK][68];    // [k][m], padded
    __shared__ float Bs[BK][260];   // [k][n], padded

    const int tid  = threadIdx.x;
    const int row0 = blockIdx.x * BM;
    const int tm   = tid >> 5;          // 0..7
    const int tn   = tid & 31;          // 0..31

    const int am = tid >> 2;            // 0..63
    const int ak = (tid & 3) << 2;      // 0,4,8,12
    const int bk = tid >> 4;            // 0..15
    const int bq = tid & 15;            // 0..15

    const int  arow   = row0 + am;
    const bool avalid = (arow < n_nodes);

    unsigned long long acc[8][4];
    #pragma unroll
    for (int i = 0; i < 8; i++)
        #pragma unroll
        for (int j = 0; j < 4; j++) acc[i][j] = 0ull;

    for (int kt = 0; kt < 2 * D; kt += BK) {
        // ---- load A tile (g_agg for kt<256, xin for kt>=256) ----
        float4 av = make_float4(0.f, 0.f, 0.f, 0.f);
        if (avalid) {
            if (kt < D)
                av = *(const float4*)(g_agg + (size_t)arow * D + kt + ak);
            else
                av = *(const float4*)(xin + (size_t)arow * D + (kt - D) + ak);
        }
        As[ak + 0][am] = av.x;
        As[ak + 1][am] = av.y;
        As[ak + 2][am] = av.z;
        As[ak + 3][am] = av.w;

        // ---- load B tile ----
        const float* W = (kt < D) ? Wl : Wr;
        const int krow = (kt & (D - 1)) + bk;
        const float* wrow = W + (size_t)krow * D;
        #pragma unroll
        for (int q = 0; q < 4; q++) {
            int n0 = bq * 4 + q * 64;
            *(float4*)&Bs[bk][n0] = *(const float4*)(wrow + n0);
        }
        __syncthreads();

        // ---- compute ----
        #pragma unroll
        for (int kk = 0; kk < BK; kk++) {
            const unsigned long long* bp =
                (const unsigned long long*)&Bs[kk][tn << 3];
            unsigned long long rb0 = bp[0], rb1 = bp[1], rb2 = bp[2], rb3 = bp[3];
            const float* ap = &As[kk][tm << 3];
            #pragma unroll
            for (int i = 0; i < 8; i++) {
                unsigned ua = __float_as_uint(ap[i]);
                unsigned long long a2;
                asm("mov.b64 %0, {%1, %1};" : "=l"(a2) : "r"(ua));
                asm("fma.rn.f32x2 %0, %1, %2, %0;" : "+l"(acc[i][0]) : "l"(a2), "l"(rb0));
                asm("fma.rn.f32x2 %0, %1, %2, %0;" : "+l"(acc[i][1]) : "l"(a2), "l"(rb1));
                asm("fma.rn.f32x2 %0, %1, %2, %0;" : "+l"(acc[i][2]) : "l"(a2), "l"(rb2));
                asm("fma.rn.f32x2 %0, %1, %2, %0;" : "+l"(acc[i][3]) : "l"(a2), "l"(rb3));
            }
        }
        __syncthreads();
    }

    // ---- epilogue: bias (+ReLU), write out ----
    const int col0 = tn << 3;
    float4 bb0 = *(const float4*)(bias + col0);
    float4 bb1 = *(const float4*)(bias + col0 + 4);
    const float bv[8] = {bb0.x, bb0.y, bb0.z, bb0.w, bb1.x, bb1.y, bb1.z, bb1.w};

    #pragma unroll
    for (int i = 0; i < 8; i++) {
        int row = row0 + (tm << 3) + i;
        if (row >= n_nodes) continue;
        float v[8];
        #pragma unroll
        for (int j = 0; j < 4; j++) {
            unsigned lo, hi;
            asm("mov.b64 {%0, %1}, %2;" : "=r"(lo), "=r"(hi) : "l"(acc[i][j]));
            v[2 * j]     = __uint_as_float(lo) + bv[2 * j];
            v[2 * j + 1] = __uint_as_float(hi) + bv[2 * j + 1];
        }
        if (do_relu) {
            #pragma unroll
            for (int j = 0; j < 8; j++) v[j] = fmaxf(v[j], 0.0f);
        }
        float* op = out + (size_t)row * D + col0;
        *(float4*)op       = make_float4(v[0], v[1], v[2], v[3]);
        *(float4*)(op + 4) = make_float4(v[4], v[5], v[6], v[7]);
    }
}

// ---------------- launch ----------------
extern "C" void kernel_launch(void* const* d_in, const int* in_sizes, int n_in,
                              void* d_out, int out_size) {
    const float* x   = (const float*)d_in[0];
    const int*   raw = (const int*)d_in[1];
    const float* W1l = (const float*)d_in[2];
    const float* b1  = (const float*)d_in[3];
    const float* W1r = (const float*)d_in[4];
    const float* W2l = (const float*)d_in[5];
    const float* b2  = (const float*)d_in[6];
    const float* W2r = (const float*)d_in[7];
    float* out = (float*)d_out;

    const int n_nodes = in_sizes[0] / D;
    const int n_edges = in_sizes[1] / 2;

    float* hptr;
    cudaGetSymbolAddress((void**)&hptr, g_h);

    const int gemm_blocks = (n_nodes + BM - 1) / BM;
    const int agg_blocks  = (n_nodes * 32 + 255) / 256;
    const int eb = (n_edges + 255) / 256;
    const int nb = (n_nodes + 255) / 256;

    // ---- edge dtype detect + decode ----
    zero_flag_kernel<<<1, 1>>>();
    detect_kernel<<<eb, 256>>>(raw, n_edges);
    extract_kernel<<<eb, 256>>>(raw, n_edges, n_nodes);

    // ---- CSR build (reused by both layers) ----
    zero_cnt_kernel<<<nb, 256>>>(n_nodes);
    count_kernel<<<eb, 256>>>(n_edges);
    scan_kernel<<<1, 1024>>>(n_nodes);
    build_kernel<<<eb, 256>>>(n_edges);

    // ---- layer 1 ----
    aggregate_kernel<<<agg_blocks, 256>>>(x, n_nodes);
    sage_gemm_kernel<<<gemm_blocks, 256>>>(x, W1l, b1, W1r, hptr, n_nodes, 1);

    // ---- layer 2 ----
    aggregate_kernel<<<agg_blocks, 256>>>(hptr, n_nodes);
    sage_gemm_kernel<<<gemm_blocks, 256>>>(hptr, W2l, b2, W2r, out, n_nodes, 0);
}